// round 1
// baseline (speedup 1.0000x reference)
#include <cuda_runtime.h>

// LossMIDU: mean over 4-connected components of tanh(x)>0 mask of
//   sum(tanh(x) in comp) / (N+1 - count(comp))
// Implemented as atomic union-find CCL + scattered accumulation + reduction.

static constexpr int E    = 4096;
static constexpr int NPIX = E * E;          // 16,777,216

// Scratch (statically allocated device globals — no runtime allocation).
__device__ int    g_parent[NPIX];
__device__ float  g_sum[NPIX];
__device__ int    g_cnt[NPIX];
__device__ double g_total;
__device__ double g_ncomp;

__global__ void k_init() {
    int i = blockIdx.x * blockDim.x + threadIdx.x;
    if (i < NPIX) {
        g_parent[i] = i;
        g_sum[i]    = 0.0f;
        g_cnt[i]    = 0;
    }
    if (i == 0) { g_total = 0.0; g_ncomp = 0.0; }
}

// Path-halving find. Links only ever point to strictly smaller indices
// (min-root convention), so traversal is finite and halving stores are
// always valid-ancestor writes.
__device__ __forceinline__ int find_root(int i) {
    int p = g_parent[i];
    if (p == i) return i;
    while (true) {
        int gp = g_parent[p];
        if (gp == p) return p;
        g_parent[i] = gp;   // path halving (monotone toward root, race-safe)
        i = p;
        p = gp;
    }
}

__device__ __forceinline__ void unite(int a, int b) {
    int ra = find_root(a);
    int rb = find_root(b);
    while (ra != rb) {
        if (ra > rb) { int t = ra; ra = rb; rb = t; }
        // Only link a node while it is still its own root (coherent CAS).
        int old = atomicCAS(&g_parent[rb], rb, ra);
        if (old == rb) return;
        rb = find_root(old);
    }
}

__global__ void k_merge(const float* __restrict__ x) {
    int i = blockIdx.x * blockDim.x + threadIdx.x;
    if (i >= NPIX) return;
    float xv = x[i];
    if (xv <= 0.0f) return;                  // mask = tanh(x)>0 == x>0
    int c = i & (E - 1);
    if (c + 1 < E && x[i + 1] > 0.0f) unite(i, i + 1);
    if (i + E < NPIX && x[i + E] > 0.0f) unite(i, i + E);
}

__global__ void k_accum(const float* __restrict__ x) {
    int i = blockIdx.x * blockDim.x + threadIdx.x;
    if (i >= NPIX) return;
    float xv = x[i];
    if (xv <= 0.0f) return;
    int r = find_root(i);
    atomicAdd(&g_sum[r], tanhf(xv));
    atomicAdd(&g_cnt[r], 1);
}

__global__ void k_final() {
    int i = blockIdx.x * blockDim.x + threadIdx.x;
    double t = 0.0, c = 0.0;
    if (i < NPIX) {
        int cnt = g_cnt[i];
        if (cnt > 0) {
            // Match reference float32 arithmetic: (N+1 - count) in fp32.
            float denom = (float)(NPIX + 1) - (float)cnt;
            t = (double)(g_sum[i] / denom);
            c = 1.0;
        }
    }
    // Warp reduce
    #pragma unroll
    for (int off = 16; off; off >>= 1) {
        t += __shfl_down_sync(0xffffffffu, t, off);
        c += __shfl_down_sync(0xffffffffu, c, off);
    }
    __shared__ double st[8], sc[8];
    int lane = threadIdx.x & 31;
    int w    = threadIdx.x >> 5;
    if (lane == 0) { st[w] = t; sc[w] = c; }
    __syncthreads();
    if (w == 0) {
        int nw = blockDim.x >> 5;
        t = (lane < nw) ? st[lane] : 0.0;
        c = (lane < nw) ? sc[lane] : 0.0;
        #pragma unroll
        for (int off = 4; off; off >>= 1) {
            t += __shfl_down_sync(0xffffffffu, t, off);
            c += __shfl_down_sync(0xffffffffu, c, off);
        }
        if (lane == 0) {
            atomicAdd(&g_total, t);
            atomicAdd(&g_ncomp, c);
        }
    }
}

__global__ void k_write(float* __restrict__ out) {
    out[0] = (g_ncomp > 0.0) ? (float)(g_total / g_ncomp) : 0.0f;
}

extern "C" void kernel_launch(void* const* d_in, const int* in_sizes, int n_in,
                              void* d_out, int out_size) {
    const float* x   = (const float*)d_in[0];
    float*       out = (float*)d_out;

    const int threads = 256;
    const int blocks  = (NPIX + threads - 1) / threads;

    k_init <<<blocks, threads>>>();
    k_merge<<<blocks, threads>>>(x);
    k_accum<<<blocks, threads>>>(x);
    k_final<<<blocks, threads>>>();
    k_write<<<1, 1>>>(out);
}

// round 2
// speedup vs baseline: 1.7594x; 1.7594x over previous
#include <cuda_runtime.h>

// LossMIDU: mean over 4-connected components of the tanh(x)>0 mask of
//   sum(tanh(x) in comp) / (N+1 - count(comp)).
// Run-based union-find CCL:
//   k_init : parent[i] = start of horizontal run (warp-scan, no atomics) + zero scratch
//   k_merge: vertical CAS unions only, one per adjacent run-pair (leftmost overlap)
//   k_accum: one find + 2 atomics per horizontal run
//   k_final: vectorized scan of roots, block-reduced
//   k_write: final scalar

static constexpr int E    = 4096;
static constexpr int NPIX = E * E;

__device__ int    g_parent[NPIX];
__device__ float  g_sum[NPIX];
__device__ int    g_cnt[NPIX];
__device__ double g_total;
__device__ double g_ncomp;

// Path-halving find. Links always point to strictly smaller indices.
__device__ __forceinline__ int find_root(int i) {
    int p = g_parent[i];
    if (p == i) return i;
    while (true) {
        int gp = g_parent[p];
        if (gp == p) return p;
        g_parent[i] = gp;   // path halving (monotone toward root, race-safe)
        i = p;
        p = gp;
    }
}

__device__ __forceinline__ void unite(int a, int b) {
    int ra = find_root(a);
    int rb = find_root(b);
    while (ra != rb) {
        if (ra > rb) { int t = ra; ra = rb; rb = t; }
        int old = atomicCAS(&g_parent[rb], rb, ra);
        if (old == rb) return;
        rb = find_root(old);
    }
}

// parent[i] = horizontal run start, computed with a warp-wide max-scan over
// 128-pixel windows (rows are multiples of 128, so windows never span rows).
// Runs crossing a window boundary chain via the window-base pixel -> base-1.
__global__ void k_init(const float* __restrict__ x) {
    int chunk = blockIdx.x * blockDim.x + threadIdx.x;
    int base  = chunk << 2;
    float4 xv = reinterpret_cast<const float4*>(x)[chunk];
    float v[4] = {xv.x, xv.y, xv.z, xv.w};
    unsigned m = 0;
    #pragma unroll
    for (int j = 0; j < 4; j++) m |= (unsigned)(v[j] > 0.0f) << j;

    int lane  = threadIdx.x & 31;
    int wbase = base - (lane << 2);          // 128-aligned window base
    unsigned zeros = (~m) & 0xFu;
    // absolute position of last zero in this chunk; identity = wbase-1
    int lz = zeros ? (base + 31 - __clz(zeros)) : (wbase - 1);

    int incl = lz;
    #pragma unroll
    for (int off = 1; off < 32; off <<= 1) {
        int t = __shfl_up_sync(0xffffffffu, incl, off);
        if (lane >= off) incl = max(incl, t);
    }
    int excl = __shfl_up_sync(0xffffffffu, incl, 1);
    if (lane == 0) excl = wbase - 1;

    int p[4];
    int prevz = excl;                         // last zero strictly before pixel
    #pragma unroll
    for (int j = 0; j < 4; j++) {
        int i = base + j;
        if ((m >> j) & 1u) {
            int pj = prevz + 1;               // run start within window
            // window-base pixel: chain into previous window if run continues
            if (i == wbase && (i & (E - 1)) != 0 && x[i - 1] > 0.0f) pj = i - 1;
            p[j] = pj;
        } else {
            p[j] = i;
            prevz = i;
        }
    }
    reinterpret_cast<int4*>(g_parent)[chunk] = make_int4(p[0], p[1], p[2], p[3]);
    reinterpret_cast<float4*>(g_sum)[chunk]  = make_float4(0.f, 0.f, 0.f, 0.f);
    reinterpret_cast<int4*>(g_cnt)[chunk]    = make_int4(0, 0, 0, 0);
    if (chunk == 0) { g_total = 0.0; g_ncomp = 0.0; }
}

// Vertical unions only. Suppress redundant unions: for a pair of vertically
// overlapping runs, union only at the leftmost overlap column.
__global__ void k_merge(const float* __restrict__ x) {
    int chunk = blockIdx.x * blockDim.x + threadIdx.x;
    int base  = E + (chunk << 2);
    const float4* x4 = reinterpret_cast<const float4*>(x);
    float4 c4 = x4[base >> 2];
    float4 u4 = x4[(base - E) >> 2];
    float c[4] = {c4.x, c4.y, c4.z, c4.w};
    float u[4] = {u4.x, u4.y, u4.z, u4.w};
    int   lane = threadIdx.x & 31;
    float cl = __shfl_up_sync(0xffffffffu, c4.w, 1);
    float ul = __shfl_up_sync(0xffffffffu, u4.w, 1);
    int colbase = base & (E - 1);

    #pragma unroll
    for (int j = 0; j < 4; j++) {
        if (c[j] > 0.0f && u[j] > 0.0f) {
            bool skip;
            if (j > 0)            skip = (c[j-1] > 0.0f && u[j-1] > 0.0f);
            else if (colbase == 0) skip = false;               // row start: no left
            else if (lane > 0)     skip = (cl > 0.0f && ul > 0.0f);
            else                   skip = false;               // unknown left: union anyway (redundant ok)
            if (!skip) unite(base + j, base + j - E);
        }
    }
}

// One find + two atomics per horizontal run; run start = positive with
// non-positive (or row-edge) left neighbor.
__global__ void k_accum(const float* __restrict__ x) {
    int chunk = blockIdx.x * blockDim.x + threadIdx.x;
    int base  = chunk << 2;
    float4 xv = reinterpret_cast<const float4*>(x)[chunk];
    float v[4] = {xv.x, xv.y, xv.z, xv.w};
    int lane    = threadIdx.x & 31;
    float lw    = __shfl_up_sync(0xffffffffu, xv.w, 1);
    int colbase = base & (E - 1);
    float left0;
    if (colbase == 0)   left0 = -1.0f;
    else if (lane > 0)  left0 = lw;
    else                left0 = x[base - 1];

    #pragma unroll
    for (int j = 0; j < 4; j++) {
        float lv = j ? v[j-1] : left0;
        if (v[j] > 0.0f && lv <= 0.0f) {
            int   i   = base + j;
            int   col = colbase + j;
            float s   = 0.0f;
            int   len = 0;
            float cur = v[j];
            while (true) {
                s += tanhf(cur);
                len++;
                if (col + len >= E) break;
                cur = (j + len < 4) ? v[j + len] : x[i + len];
                if (cur <= 0.0f) break;
            }
            int r = find_root(i);
            atomicAdd(&g_sum[r], s);
            atomicAdd(&g_cnt[r], len);
        }
    }
}

__global__ void k_final() {
    int chunk = blockIdx.x * blockDim.x + threadIdx.x;
    double t = 0.0, c = 0.0;
    int4 cn = reinterpret_cast<const int4*>(g_cnt)[chunk];
    if (cn.x | cn.y | cn.z | cn.w) {
        float4 sv = reinterpret_cast<const float4*>(g_sum)[chunk];
        int   cc[4] = {cn.x, cn.y, cn.z, cn.w};
        float ss[4] = {sv.x, sv.y, sv.z, sv.w};
        #pragma unroll
        for (int j = 0; j < 4; j++) {
            if (cc[j] > 0) {
                float denom = (float)(NPIX + 1) - (float)cc[j];   // fp32 like reference
                t += (double)(ss[j] / denom);
                c += 1.0;
            }
        }
    }
    #pragma unroll
    for (int off = 16; off; off >>= 1) {
        t += __shfl_down_sync(0xffffffffu, t, off);
        c += __shfl_down_sync(0xffffffffu, c, off);
    }
    __shared__ double st[8], sc[8];
    int lane = threadIdx.x & 31;
    int w    = threadIdx.x >> 5;
    if (lane == 0) { st[w] = t; sc[w] = c; }
    __syncthreads();
    if (w == 0) {
        int nw = blockDim.x >> 5;
        t = (lane < nw) ? st[lane] : 0.0;
        c = (lane < nw) ? sc[lane] : 0.0;
        #pragma unroll
        for (int off = 4; off; off >>= 1) {
            t += __shfl_down_sync(0xffffffffu, t, off);
            c += __shfl_down_sync(0xffffffffu, c, off);
        }
        if (lane == 0) {
            atomicAdd(&g_total, t);
            atomicAdd(&g_ncomp, c);
        }
    }
}

__global__ void k_write(float* __restrict__ out) {
    out[0] = (g_ncomp > 0.0) ? (float)(g_total / g_ncomp) : 0.0f;
}

extern "C" void kernel_launch(void* const* d_in, const int* in_sizes, int n_in,
                              void* d_out, int out_size) {
    const float* x   = (const float*)d_in[0];
    float*       out = (float*)d_out;

    const int threads = 256;
    const int chunks_all  = NPIX / 4;                 // 4,194,304
    const int chunks_merge = (NPIX - E) / 4;          // 4,190,208 (exact multiple of 256)

    k_init <<<chunks_all  / threads, threads>>>(x);
    k_merge<<<chunks_merge / threads, threads>>>(x);
    k_accum<<<chunks_all  / threads, threads>>>(x);
    k_final<<<chunks_all  / threads, threads>>>();
    k_write<<<1, 1>>>(out);
}

// round 3
// speedup vs baseline: 2.1200x; 1.2049x over previous
#include <cuda_runtime.h>

// LossMIDU: mean over 4-connected components of the tanh(x)>0 mask of
//   sum(tanh(x) in comp) / (N+1 - count(comp)).
// Run-based union-find CCL with a bit-per-pixel mask:
//   k_init : parent[i] = horizontal run start (warp scan) + mask bits + zero scratch
//   k_merge: vertical CAS unions from mask words, one per overlap-run start
//   k_accum: one find + 2 atomics per horizontal run
//   k_final: vectorized root scan, block reduce, last-block writes output

static constexpr int E      = 4096;
static constexpr int NPIX   = E * E;
static constexpr int WORDS  = NPIX / 32;       // mask words
static constexpr int WPR    = E / 32;          // words per row = 128

__device__ int      g_parent[NPIX];
__device__ float    g_sum[NPIX];
__device__ int      g_cnt[NPIX];
__device__ unsigned g_mask[WORDS];
__device__ double   g_total;
__device__ double   g_ncomp;
__device__ unsigned g_done;

// Path-halving find. Links always point to strictly smaller indices.
__device__ __forceinline__ int find_root(int i) {
    int p = g_parent[i];
    if (p == i) return i;
    while (true) {
        int gp = g_parent[p];
        if (gp == p) return p;
        g_parent[i] = gp;   // path halving (monotone toward root, race-safe)
        i = p;
        p = gp;
    }
}

__device__ __forceinline__ void unite(int a, int b) {
    int ra = find_root(a);
    int rb = find_root(b);
    while (ra != rb) {
        if (ra > rb) { int t = ra; ra = rb; rb = t; }
        int old = atomicCAS(&g_parent[rb], rb, ra);
        if (old == rb) return;
        rb = find_root(old);
    }
}

// parent[i] = horizontal run start via warp max-scan over 128-pixel windows
// (windows never span rows). Also emits the bitmask and zeroes scratch.
__global__ void k_init(const float* __restrict__ x) {
    int chunk = blockIdx.x * blockDim.x + threadIdx.x;
    int base  = chunk << 2;
    float4 xv = reinterpret_cast<const float4*>(x)[chunk];
    float v[4] = {xv.x, xv.y, xv.z, xv.w};
    unsigned m = 0;
    #pragma unroll
    for (int j = 0; j < 4; j++) m |= (unsigned)(v[j] > 0.0f) << j;

    // mask word assembly: 8 nibbles -> 1 word
    __shared__ unsigned char s_nib[256];
    s_nib[threadIdx.x] = (unsigned char)m;

    int lane  = threadIdx.x & 31;
    int wbase = base - (lane << 2);            // 128-aligned window base
    unsigned zeros = (~m) & 0xFu;
    int lz = zeros ? (base + 31 - __clz(zeros)) : (wbase - 1);

    int incl = lz;
    #pragma unroll
    for (int off = 1; off < 32; off <<= 1) {
        int t = __shfl_up_sync(0xffffffffu, incl, off);
        if (lane >= off) incl = max(incl, t);
    }
    int excl = __shfl_up_sync(0xffffffffu, incl, 1);
    if (lane == 0) excl = wbase - 1;

    int p[4];
    int prevz = excl;
    #pragma unroll
    for (int j = 0; j < 4; j++) {
        int i = base + j;
        if ((m >> j) & 1u) {
            int pj = prevz + 1;
            if (i == wbase && (i & (E - 1)) != 0 && x[i - 1] > 0.0f) pj = i - 1;
            p[j] = pj;
        } else {
            p[j] = i;
            prevz = i;
        }
    }
    reinterpret_cast<int4*>(g_parent)[chunk] = make_int4(p[0], p[1], p[2], p[3]);
    reinterpret_cast<float4*>(g_sum)[chunk]  = make_float4(0.f, 0.f, 0.f, 0.f);
    reinterpret_cast<int4*>(g_cnt)[chunk]    = make_int4(0, 0, 0, 0);

    __syncthreads();
    if (threadIdx.x < 32) {
        unsigned w = 0;
        #pragma unroll
        for (int k = 0; k < 8; k++)
            w |= (unsigned)s_nib[threadIdx.x * 8 + k] << (4 * k);
        g_mask[blockIdx.x * 32 + threadIdx.x] = w;
    }
    if (chunk == 0) { g_total = 0.0; g_ncomp = 0.0; g_done = 0u; }
}

// Vertical unions from mask words: one block per row (rows 1..E-1),
// one 32-pixel word per thread. Union once per overlap-run start.
__global__ void __launch_bounds__(WPR) k_merge() {
    int row  = blockIdx.x + 1;
    int wcol = threadIdx.x;                    // 0..127
    int widx = row * WPR + wcol;
    unsigned wc = g_mask[widx];
    unsigned wu = g_mask[widx - WPR];
    unsigned ov = wc & wu;
    if (!ov) return;

    int lane = threadIdx.x & 31;
    unsigned cl = __shfl_up_sync(0xffffffffu, wc, 1);
    unsigned ul = __shfl_up_sync(0xffffffffu, wu, 1);
    unsigned carry = 0;
    if (wcol > 0) {
        if (lane == 0) {                       // warp edge: fetch left words
            cl = g_mask[widx - 1];
            ul = g_mask[widx - 1 - WPR];
        }
        carry = (cl >> 31) & (ul >> 31) & 1u;
    }
    unsigned starts = ov & ~((ov << 1) | carry);

    int base = row * E + (wcol << 5);
    while (starts) {
        int b = __ffs(starts) - 1;
        starts &= starts - 1;
        unite(base + b, base + b - E);
    }
}

// One find + two atomics per horizontal run.
__global__ void k_accum(const float* __restrict__ x) {
    int chunk = blockIdx.x * blockDim.x + threadIdx.x;
    int base  = chunk << 2;
    float4 xv = reinterpret_cast<const float4*>(x)[chunk];
    float v[4] = {xv.x, xv.y, xv.z, xv.w};
    int lane    = threadIdx.x & 31;
    float lw    = __shfl_up_sync(0xffffffffu, xv.w, 1);
    int colbase = base & (E - 1);
    float left0;
    if (colbase == 0)   left0 = -1.0f;
    else if (lane > 0)  left0 = lw;
    else                left0 = x[base - 1];

    #pragma unroll
    for (int j = 0; j < 4; j++) {
        float lv = j ? v[j-1] : left0;
        if (v[j] > 0.0f && lv <= 0.0f) {
            int   i   = base + j;
            int   col = colbase + j;
            float s   = 0.0f;
            int   len = 0;
            float cur = v[j];
            while (true) {
                s += tanhf(cur);
                len++;
                if (col + len >= E) break;
                cur = (j + len < 4) ? v[j + len] : x[i + len];
                if (cur <= 0.0f) break;
            }
            int r = find_root(i);
            atomicAdd(&g_sum[r], s);
            atomicAdd(&g_cnt[r], len);
        }
    }
}

__global__ void k_final(float* __restrict__ out) {
    int chunk = blockIdx.x * blockDim.x + threadIdx.x;
    double t = 0.0, c = 0.0;
    int4 cn = reinterpret_cast<const int4*>(g_cnt)[chunk];
    if (cn.x | cn.y | cn.z | cn.w) {
        float4 sv = reinterpret_cast<const float4*>(g_sum)[chunk];
        int   cc[4] = {cn.x, cn.y, cn.z, cn.w};
        float ss[4] = {sv.x, sv.y, sv.z, sv.w};
        #pragma unroll
        for (int j = 0; j < 4; j++) {
            if (cc[j] > 0) {
                float denom = (float)(NPIX + 1) - (float)cc[j];   // fp32 like reference
                t += (double)(ss[j] / denom);
                c += 1.0;
            }
        }
    }
    #pragma unroll
    for (int off = 16; off; off >>= 1) {
        t += __shfl_down_sync(0xffffffffu, t, off);
        c += __shfl_down_sync(0xffffffffu, c, off);
    }
    __shared__ double st[8], sc[8];
    int lane = threadIdx.x & 31;
    int w    = threadIdx.x >> 5;
    if (lane == 0) { st[w] = t; sc[w] = c; }
    __syncthreads();
    if (w == 0) {
        int nw = blockDim.x >> 5;
        t = (lane < nw) ? st[lane] : 0.0;
        c = (lane < nw) ? sc[lane] : 0.0;
        #pragma unroll
        for (int off = 4; off; off >>= 1) {
            t += __shfl_down_sync(0xffffffffu, t, off);
            c += __shfl_down_sync(0xffffffffu, c, off);
        }
        if (lane == 0) {
            atomicAdd(&g_total, t);
            atomicAdd(&g_ncomp, c);
            __threadfence();
            unsigned ticket = atomicAdd(&g_done, 1u);
            if (ticket == gridDim.x - 1) {
                double tt = *((volatile double*)&g_total);
                double nc = *((volatile double*)&g_ncomp);
                out[0] = (nc > 0.0) ? (float)(tt / nc) : 0.0f;
            }
        }
    }
}

extern "C" void kernel_launch(void* const* d_in, const int* in_sizes, int n_in,
                              void* d_out, int out_size) {
    const float* x   = (const float*)d_in[0];
    float*       out = (float*)d_out;

    const int threads    = 256;
    const int chunks_all = NPIX / 4;

    k_init <<<chunks_all / threads, threads>>>(x);
    k_merge<<<E - 1, WPR>>>();
    k_accum<<<chunks_all / threads, threads>>>(x);
    k_final<<<chunks_all / threads, threads>>>(out);
}